// round 6
// baseline (speedup 1.0000x reference)
#include <cuda_runtime.h>
#include <math.h>

#define BB 128
#define NN 128
#define RT 8
#define EDGE_BLOCKS (BB * (NN / RT))   // 2048

// ---------------------------------------------------------------------------
// Folded / quantized weights (activations carried as 256-scaled integers).
// ---------------------------------------------------------------------------
struct QWeights {
    // edge-MLP weights (42 uint4)
    unsigned W2p[15][8];
    int b2i[16];
    unsigned W3p[6][4];
    int b3i[8];
    // fo weights, input-major (598 uint4 chunk, cp.async'd to smem)
    float Wo1s[22][48];
    float bo1[48];
    float Wo2s[45][24];
    float bo2[24];
    float Wo3s[22][8];
    float bo3[8];
    // head
    float Wc1t[48][8];
    float bc1[48];
    float Wc2t[5][48];
    float bc2[8];
};

__device__ QWeights g_qw;
__device__ __align__(16) float g_bn[BB * NN * 16];
__device__ __align__(16) float g_Ar[BB * NN * 32];
__device__ __align__(16) float g_As[BB * NN * 32];
__device__ float g_part[BB][NN / RT][6];
__device__ unsigned g_ticket;

__device__ __forceinline__ float qb(float x) {
    float y = fminf(fmaxf(x, -1.0f), 127.0f / 128.0f);
    return rintf(y * 128.0f) * (1.0f / 128.0f);
}
__device__ __forceinline__ int qm(float x) {
    float y = fminf(fmaxf(x, -1.0f), 127.0f / 128.0f);
    return (int)rintf(y * 128.0f);
}
__device__ __forceinline__ float qreluF(float p) {
    return rintf(fminf(fmaxf(p, 0.0f), 255.0f));
}
__device__ __forceinline__ unsigned cvt_u8(float x) {
    unsigned short h;
    asm("cvt.rni.sat.u8.f32 %0, %1;" : "=h"(h) : "f"(x));
    return (unsigned)h;
}
__device__ __forceinline__ unsigned requant(int acc) {
    return cvt_u8((float)acc * (1.0f / 128.0f));
}
__device__ __forceinline__ unsigned pk4(unsigned a, unsigned b, unsigned c, unsigned d) {
    return __byte_perm(__byte_perm(a, b, 0x0040), __byte_perm(c, d, 0x0040), 0x5410);
}
__device__ __forceinline__ int dp4a_us(unsigned a, unsigned b, int c) {
    int d;
    asm("dp4a.u32.s32 %0, %1, %2, %3;" : "=r"(d) : "r"(a), "r"(b), "r"(c));
    return d;
}
__device__ __forceinline__ void cp_async16(void* smem_dst, const void* gsrc) {
    unsigned saddr = (unsigned)__cvta_generic_to_shared(smem_dst);
    asm volatile("cp.async.cg.shared.global [%0], [%1], 16;" :: "r"(saddr), "l"(gsrc));
}

// ---------------------------------------------------------------------------
// Fused pre kernel: blocks [0,BB) per-node bn/Ar/As; blocks [BB,BB+4) weights.
// ---------------------------------------------------------------------------
__global__ void __launch_bounds__(256) fused_pre_kernel(
    const float* __restrict__ x,
    const float* __restrict__ gamma, const float* __restrict__ beta,
    const float* __restrict__ mean,  const float* __restrict__ var,
    const float* __restrict__ fr_w1, const float* __restrict__ fr_b1,
    const float* __restrict__ fr_w2, const float* __restrict__ fr_b2,
    const float* __restrict__ fr_w3, const float* __restrict__ fr_b3,
    const float* __restrict__ fo_w1, const float* __restrict__ fo_b1,
    const float* __restrict__ fo_w2, const float* __restrict__ fo_b2,
    const float* __restrict__ fo_w3, const float* __restrict__ fo_b3,
    const float* __restrict__ fc_w1, const float* __restrict__ fc_b1,
    const float* __restrict__ fc_w2, const float* __restrict__ fc_b2)
{
    const int t = threadIdx.x;
    const int blk = blockIdx.x;

    if (blk >= BB) {
        const int sec = blk - BB;
        if (sec == 0) {
            for (int i = t; i < 15 * 8; i += 256) {
                int k = i / 8, j4 = i % 8;
                unsigned p = 0;
                for (int u = 0; u < 4; u++) {
                    int j = j4 * 4 + u;
                    int m = (j < 30) ? qm(fr_w2[j * 15 + k]) : 0;
                    p |= ((unsigned)(m & 255)) << (8 * u);
                }
                g_qw.W2p[k][j4] = p;
            }
            if (t < 16) g_qw.b2i[t] = (t < 15) ? 256 * qm(fr_b2[t]) : 0;
            for (int i = t; i < 6 * 4; i += 256) {
                int c = i / 4, j4 = i % 4;
                unsigned p = 0;
                for (int u = 0; u < 4; u++) {
                    int j = j4 * 4 + u;
                    int m = (j < 15) ? qm(fr_w3[j * 6 + c]) : 0;
                    p |= ((unsigned)(m & 255)) << (8 * u);
                }
                g_qw.W3p[c][j4] = p;
            }
            if (t < 8) g_qw.b3i[t] = (t < 6) ? 256 * qm(fr_b3[t]) : 0;
        } else if (sec == 1) {
            for (int i = t; i < 22 * 48; i += 256) {
                int j = i / 48, k = i % 48;
                float v = (k < 45) ? qb(fo_w1[j * 45 + k]) : 0.0f;
                g_qw.Wo1s[j][k] = (j < 16) ? 256.0f * v : v;
            }
            if (t < 48) g_qw.bo1[t] = (t < 45) ? 256.0f * qb(fo_b1[t]) : 0.0f;
        } else if (sec == 2) {
            for (int i = t; i < 45 * 24; i += 256) {
                int j = i / 24, k = i % 24;
                g_qw.Wo2s[j][k] = (k < 22) ? qb(fo_w2[j * 22 + k]) : 0.0f;
            }
            if (t < 24) g_qw.bo2[t] = (t < 22) ? 256.0f * qb(fo_b2[t]) : 0.0f;
        } else {
            for (int i = t; i < 22 * 8; i += 256) {
                int j = i / 8, c = i % 8;
                g_qw.Wo3s[j][c] = (c < 6) ? qb(fo_w3[j * 6 + c]) : 0.0f;
            }
            if (t < 8) g_qw.bo3[t] = (t < 6) ? 256.0f * qb(fo_b3[t]) : 0.0f;
            for (int i = t; i < 48 * 8; i += 256) {
                int k = i / 8, c = i % 8;
                g_qw.Wc1t[k][c] = (c < 6) ? qb(fc_w1[c * 48 + k]) : 0.0f;
            }
            if (t < 48) g_qw.bc1[t] = 256.0f * qb(fc_b1[t]);
            for (int i = t; i < 5 * 48; i += 256) {
                int o = i / 48, k = i % 48;
                g_qw.Wc2t[o][k] = qb(fc_w2[k * 5 + o]) * (1.0f / 256.0f);
            }
            if (t < 8) g_qw.bc2[t] = (t < 5) ? qb(fc_b2[t]) : 0.0f;
        }
        return;
    }

    // ---- per-node bn / Ar / As ----
    __shared__ __align__(16) float sW1[32 * 32];
    __shared__ float sb1[32];
    __shared__ float sA[16], sB[16];
    const int b = blk;

    for (int i = t; i < 1024; i += 256) {
        int j = i >> 5, k = i & 31;
        sW1[i] = (k < 30) ? 256.0f * qb(fr_w1[j * 30 + k]) : 0.0f;
    }
    if (t < 32) sb1[t] = (t < 30) ? 256.0f * qb(fr_b1[t]) : 0.0f;
    if (t < 16) {
        float s = gamma[t] / sqrtf(var[t] + 1e-3f);
        sA[t] = s;
        sB[t] = beta[t] - mean[t] * s;
    }
    __syncthreads();

    const int n = t & 127;
    const bool doAr = (t < 128);
    const float* xp = x + (size_t)(b * NN + n) * 16;
    float bn[16];
#pragma unroll
    for (int j = 0; j < 16; j++) bn[j] = xp[j] * sA[j] + sB[j];

    if (doAr) {
        float* bno = &g_bn[(size_t)(b * NN + n) * 16];
#pragma unroll
        for (int j = 0; j < 16; j++) bno[j] = bn[j];
    }

    float acc[32];
#pragma unroll
    for (int k = 0; k < 32; k++) acc[k] = doAr ? sb1[k] : 0.0f;
    const int roff = doAr ? 0 : 16;
#pragma unroll
    for (int j = 0; j < 16; j++) {
        float bj = bn[j];
        const float* wrow = &sW1[(roff + j) * 32];
#pragma unroll
        for (int k = 0; k < 32; k++) acc[k] += bj * wrow[k];
    }
    float* dst = doAr ? &g_Ar[(size_t)(b * NN + n) * 32]
                      : &g_As[(size_t)(b * NN + n) * 32];
#pragma unroll
    for (int k = 0; k < 32; k++) dst[k] = acc[k];
}

// ---------------------------------------------------------------------------
// edge kernel: senders in k-major smem (LDS.128), fo weights in smem via
// cp.async, RT=8 for wave balance, reg-capped for 6 blocks/SM.
// ---------------------------------------------------------------------------
struct EdgeW { unsigned W2p[15][8]; int b2i[16]; unsigned W3p[6][4]; int b3i[8]; };
struct FoW {
    float Wo1s[22][48]; float bo1[48];
    float Wo2s[45][24]; float bo2[24];
    float Wo3s[22][8];  float bo3[8];
};

__global__ void __launch_bounds__(128, 6) edge_kernel(float* __restrict__ out)
{
    __shared__ __align__(16) EdgeW sEw;
    __shared__ __align__(16) FoW sFo;
    __shared__ __align__(16) float4 sAs4[8][128];   // [k/4][sender]
    __shared__ __align__(16) float sAr[RT][32];
    __shared__ __align__(16) float sBn[RT][16];
    __shared__ int sEffI[RT][4];
    __shared__ float sEffF[RT][6];
    __shared__ float sHo1[RT][45];
    __shared__ float sHo2[RT][22];
    __shared__ float sPool[8];
    __shared__ unsigned sLast;

    const int t = threadIdx.x;
    const int rg = blockIdx.x, b = blockIdx.y;
    const int r0 = rg * RT;

    // fo weights ride under the main loop via cp.async
    {
        const uint4* fs = reinterpret_cast<const uint4*>(&g_qw.Wo1s[0][0]);
        uint4* fd = reinterpret_cast<uint4*>(&sFo);
        for (int i = t; i < 598; i += 128) cp_async16(&fd[i], &fs[i]);
        asm volatile("cp.async.commit_group;");
    }
    {
        const uint4* es = reinterpret_cast<const uint4*>(&g_qw);
        uint4* ed = reinterpret_cast<uint4*>(&sEw);
        if (t < 42) ed[t] = es[t];
        const uint4* ars = reinterpret_cast<const uint4*>(&g_Ar[(size_t)(b * NN + r0) * 32]);
        uint4* ard = reinterpret_cast<uint4*>(&sAr[0][0]);
        if (t < RT * 8) ard[t] = ars[t];
        const uint4* bns = reinterpret_cast<const uint4*>(&g_bn[(size_t)(b * NN + r0) * 16]);
        uint4* bnd = reinterpret_cast<uint4*>(&sBn[0][0]);
        if (t < RT * 4) bnd[t] = bns[t];
        if (t < RT * 4) (&sEffI[0][0])[t] = 0;
        if (t < 8) sPool[t] = 0.0f;
    }
    // sender activations -> k-major float4 smem
    {
        const float4* p = reinterpret_cast<const float4*>(&g_As[(size_t)(b * NN + t) * 32]);
#pragma unroll
        for (int j = 0; j < 8; j++) sAs4[j][t] = p[j];
    }
    __syncthreads();

#pragma unroll 1
    for (int rr = 0; rr < RT; rr++) {
        const float4* a4 = reinterpret_cast<const float4*>(&sAr[rr][0]);

        unsigned h1p[8];
#pragma unroll
        for (int j = 0; j < 8; j++) {
            float4 av = a4[j];        // broadcast LDS
            float4 sv = sAs4[j][t];   // own-column LDS.128
            unsigned u0 = cvt_u8(av.x + sv.x);
            unsigned u1 = cvt_u8(av.y + sv.y);
            unsigned u2 = cvt_u8(av.z + sv.z);
            unsigned u3 = cvt_u8(av.w + sv.w);
            h1p[j] = pk4(u0, u1, u2, u3);
        }

        // layer 2: 15 neurons, packed immediately in groups of 4
        unsigned h2p[4];
#pragma unroll
        for (int g = 0; g < 4; g++) {
            const int nk = (g < 3) ? 4 : 3;
            unsigned qg[4];
#pragma unroll
            for (int u = 0; u < 4; u++) {
                if (u < nk) {
                    int k = g * 4 + u;
                    const uint4* w = reinterpret_cast<const uint4*>(&sEw.W2p[k][0]);
                    uint4 wa = w[0], wb = w[1];
                    int acc = sEw.b2i[k];
                    acc = dp4a_us(h1p[0], wa.x, acc);
                    acc = dp4a_us(h1p[1], wa.y, acc);
                    acc = dp4a_us(h1p[2], wa.z, acc);
                    acc = dp4a_us(h1p[3], wa.w, acc);
                    acc = dp4a_us(h1p[4], wb.x, acc);
                    acc = dp4a_us(h1p[5], wb.y, acc);
                    acc = dp4a_us(h1p[6], wb.z, acc);
                    acc = dp4a_us(h1p[7], wb.w, acc);
                    qg[u] = requant(acc);
                } else {
                    qg[u] = 0u;
                }
            }
            h2p[g] = pk4(qg[0], qg[1], qg[2], qg[3]);
        }

        // layer 3: 6 effect channels
        unsigned e[6];
#pragma unroll
        for (int c = 0; c < 6; c++) {
            uint4 w = *reinterpret_cast<const uint4*>(&sEw.W3p[c][0]);
            int acc = sEw.b3i[c];
            acc = dp4a_us(h2p[0], w.x, acc);
            acc = dp4a_us(h2p[1], w.y, acc);
            acc = dp4a_us(h2p[2], w.z, acc);
            acc = dp4a_us(h2p[3], w.w, acc);
            e[c] = requant(acc);
        }
        const bool diag = (t == r0 + rr);
        int p01 = diag ? 0 : (int)__byte_perm(e[0], e[1], 0x7430);
        int p23 = diag ? 0 : (int)__byte_perm(e[2], e[3], 0x7430);
        int p45 = diag ? 0 : (int)__byte_perm(e[4], e[5], 0x7430);
        p01 = __reduce_add_sync(0xffffffffu, p01);
        p23 = __reduce_add_sync(0xffffffffu, p23);
        p45 = __reduce_add_sync(0xffffffffu, p45);
        if ((t & 31) == 0) {
            atomicAdd(&sEffI[rr][0], p01);
            atomicAdd(&sEffI[rr][1], p23);
            atomicAdd(&sEffI[rr][2], p45);
        }
    }
    asm volatile("cp.async.wait_group 0;");
    __syncthreads();

    if (t < RT * 6) {
        int node = t / 6, c = t % 6;
        int v = sEffI[node][c >> 1];
        sEffF[node][c] = (float)((c & 1) ? ((v >> 16) & 0xFFFF) : (v & 0xFFFF));
    }
    __syncthreads();

    // fo tail from smem
    for (int idx = t; idx < RT * 45; idx += 128) {
        int node = idx / 45, k = idx % 45;
        float a = sFo.bo1[k];
#pragma unroll
        for (int j = 0; j < 16; j++) a += sBn[node][j] * sFo.Wo1s[j][k];
#pragma unroll
        for (int c = 0; c < 6; c++) a += sEffF[node][c] * sFo.Wo1s[16 + c][k];
        sHo1[node][k] = qreluF(a);
    }
    __syncthreads();
    for (int idx = t; idx < RT * 22; idx += 128) {
        int node = idx / 22, k = idx % 22;
        float a = sFo.bo2[k];
#pragma unroll
        for (int j = 0; j < 45; j++) a += sHo1[node][j] * sFo.Wo2s[j][k];
        sHo2[node][k] = qreluF(a);
    }
    __syncthreads();
    for (int idx = t; idx < RT * 6; idx += 128) {
        int node = idx / 6, c = idx % 6;
        float a = sFo.bo3[c];
#pragma unroll
        for (int j = 0; j < 22; j++) a += sHo2[node][j] * sFo.Wo3s[j][c];
        atomicAdd(&sPool[c], qreluF(a));
    }
    __syncthreads();
    if (t < 6) g_part[b][rg][t] = sPool[t];

    if (t == 0) {
        __threadfence();
        unsigned done = atomicAdd(&g_ticket, 1u);
        sLast = (done == EDGE_BLOCKS - 1) ? 1u : 0u;
    }
    __syncthreads();
    if (sLast) {
        __threadfence();
        if (t == 0) g_ticket = 0;
        const int bb = t;
        float pl[6];
#pragma unroll
        for (int c = 0; c < 6; c++) {
            float s = 0.0f;
#pragma unroll
            for (int g = 0; g < NN / RT; g++) s += g_part[bb][g][c];
            pl[c] = s;
        }
        float lg[5];
#pragma unroll
        for (int o = 0; o < 5; o++) lg[o] = g_qw.bc2[o];
#pragma unroll 4
        for (int k = 0; k < 48; k++) {
            float a = g_qw.bc1[k];
#pragma unroll
            for (int c = 0; c < 6; c++) a += pl[c] * g_qw.Wc1t[k][c];
            float c1 = qreluF(a);
#pragma unroll
            for (int o = 0; o < 5; o++) lg[o] += c1 * g_qw.Wc2t[o][k];
        }
        float m = lg[0];
#pragma unroll
        for (int o = 1; o < 5; o++) m = fmaxf(m, lg[o]);
        float ex[5], sum = 0.0f;
#pragma unroll
        for (int o = 0; o < 5; o++) { ex[o] = expf(lg[o] - m); sum += ex[o]; }
        float inv = 1.0f / sum;
#pragma unroll
        for (int o = 0; o < 5; o++) out[bb * 5 + o] = ex[o] * inv;
    }
}

// ---------------------------------------------------------------------------
extern "C" void kernel_launch(void* const* d_in, const int* in_sizes, int n_in,
                              void* d_out, int out_size)
{
    (void)in_sizes; (void)n_in; (void)out_size;

    fused_pre_kernel<<<BB + 4, 256>>>(
        (const float*)d_in[0],
        (const float*)d_in[1],  (const float*)d_in[2],
        (const float*)d_in[3],  (const float*)d_in[4],
        (const float*)d_in[5],  (const float*)d_in[6],
        (const float*)d_in[7],  (const float*)d_in[8],
        (const float*)d_in[9],  (const float*)d_in[10],
        (const float*)d_in[11], (const float*)d_in[12],
        (const float*)d_in[13], (const float*)d_in[14],
        (const float*)d_in[15], (const float*)d_in[16],
        (const float*)d_in[17], (const float*)d_in[18],
        (const float*)d_in[19], (const float*)d_in[20]);

    dim3 grid(NN / RT, BB);
    edge_kernel<<<grid, 128>>>((float*)d_out);
}

// round 7
// speedup vs baseline: 2.6845x; 2.6845x over previous
#include <cuda_runtime.h>
#include <math.h>

#define BB 128
#define NN 128
#define RT 16
#define EDGE_BLOCKS (BB * (NN / RT))   // 1024

// ---------------------------------------------------------------------------
// Folded / quantized weights (activations carried as 256-scaled integers).
// ---------------------------------------------------------------------------
struct QWeights {
    // edge-MLP weights (42 uint4)
    unsigned W2p[15][8];
    int b2i[16];
    unsigned W3p[6][4];
    int b3i[8];
    // fo weights, input-major
    float Wo1s[22][48];
    float bo1[48];
    float Wo2s[45][24];
    float bo2[24];
    float Wo3s[22][8];
    float bo3[8];
    // head
    float Wc1t[48][8];
    float bc1[48];
    float Wc2t[5][48];
    float bc2[8];
};

__device__ QWeights g_qw;
__device__ __align__(16) float g_bn[BB * NN * 16];
__device__ __align__(16) float g_Ar[BB * NN * 32];
__device__ __align__(16) float g_As[BB * NN * 32];
__device__ __align__(16) float g_eff[BB * NN * 6];

__device__ __forceinline__ float qb(float x) {
    float y = fminf(fmaxf(x, -1.0f), 127.0f / 128.0f);
    return rintf(y * 128.0f) * (1.0f / 128.0f);
}
__device__ __forceinline__ int qm(float x) {
    float y = fminf(fmaxf(x, -1.0f), 127.0f / 128.0f);
    return (int)rintf(y * 128.0f);
}
__device__ __forceinline__ float qreluF(float p) {
    return rintf(fminf(fmaxf(p, 0.0f), 255.0f));
}
__device__ __forceinline__ unsigned cvt_u8(float x) {
    unsigned short h;
    asm("cvt.rni.sat.u8.f32 %0, %1;" : "=h"(h) : "f"(x));
    return (unsigned)h;
}
__device__ __forceinline__ unsigned requant(int acc) {
    return cvt_u8((float)acc * (1.0f / 128.0f));
}
__device__ __forceinline__ unsigned pk4(unsigned a, unsigned b, unsigned c, unsigned d) {
    return __byte_perm(__byte_perm(a, b, 0x0040), __byte_perm(c, d, 0x0040), 0x5410);
}
__device__ __forceinline__ int dp4a_us(unsigned a, unsigned b, int c) {
    int d;
    asm("dp4a.u32.s32 %0, %1, %2, %3;" : "=r"(d) : "r"(a), "r"(b), "r"(c));
    return d;
}

// ---------------------------------------------------------------------------
// Fused pre kernel: blocks [0,BB) per-node bn/Ar/As; blocks [BB,BB+4) weights.
// ---------------------------------------------------------------------------
__global__ void __launch_bounds__(256) fused_pre_kernel(
    const float* __restrict__ x,
    const float* __restrict__ gamma, const float* __restrict__ beta,
    const float* __restrict__ mean,  const float* __restrict__ var,
    const float* __restrict__ fr_w1, const float* __restrict__ fr_b1,
    const float* __restrict__ fr_w2, const float* __restrict__ fr_b2,
    const float* __restrict__ fr_w3, const float* __restrict__ fr_b3,
    const float* __restrict__ fo_w1, const float* __restrict__ fo_b1,
    const float* __restrict__ fo_w2, const float* __restrict__ fo_b2,
    const float* __restrict__ fo_w3, const float* __restrict__ fo_b3,
    const float* __restrict__ fc_w1, const float* __restrict__ fc_b1,
    const float* __restrict__ fc_w2, const float* __restrict__ fc_b2)
{
    const int t = threadIdx.x;
    const int blk = blockIdx.x;

    if (blk >= BB) {
        const int sec = blk - BB;
        if (sec == 0) {
            for (int i = t; i < 15 * 8; i += 256) {
                int k = i / 8, j4 = i % 8;
                unsigned p = 0;
                for (int u = 0; u < 4; u++) {
                    int j = j4 * 4 + u;
                    int m = (j < 30) ? qm(fr_w2[j * 15 + k]) : 0;
                    p |= ((unsigned)(m & 255)) << (8 * u);
                }
                g_qw.W2p[k][j4] = p;
            }
            if (t < 16) g_qw.b2i[t] = (t < 15) ? 256 * qm(fr_b2[t]) : 0;
            for (int i = t; i < 6 * 4; i += 256) {
                int c = i / 4, j4 = i % 4;
                unsigned p = 0;
                for (int u = 0; u < 4; u++) {
                    int j = j4 * 4 + u;
                    int m = (j < 15) ? qm(fr_w3[j * 6 + c]) : 0;
                    p |= ((unsigned)(m & 255)) << (8 * u);
                }
                g_qw.W3p[c][j4] = p;
            }
            if (t < 8) g_qw.b3i[t] = (t < 6) ? 256 * qm(fr_b3[t]) : 0;
        } else if (sec == 1) {
            for (int i = t; i < 22 * 48; i += 256) {
                int j = i / 48, k = i % 48;
                float v = (k < 45) ? qb(fo_w1[j * 45 + k]) : 0.0f;
                g_qw.Wo1s[j][k] = (j < 16) ? 256.0f * v : v;
            }
            if (t < 48) g_qw.bo1[t] = (t < 45) ? 256.0f * qb(fo_b1[t]) : 0.0f;
        } else if (sec == 2) {
            for (int i = t; i < 45 * 24; i += 256) {
                int j = i / 24, k = i % 24;
                g_qw.Wo2s[j][k] = (k < 22) ? qb(fo_w2[j * 22 + k]) : 0.0f;
            }
            if (t < 24) g_qw.bo2[t] = (t < 22) ? 256.0f * qb(fo_b2[t]) : 0.0f;
        } else {
            for (int i = t; i < 22 * 8; i += 256) {
                int j = i / 8, c = i % 8;
                g_qw.Wo3s[j][c] = (c < 6) ? qb(fo_w3[j * 6 + c]) : 0.0f;
            }
            if (t < 8) g_qw.bo3[t] = (t < 6) ? 256.0f * qb(fo_b3[t]) : 0.0f;
            for (int i = t; i < 48 * 8; i += 256) {
                int k = i / 8, c = i % 8;
                g_qw.Wc1t[k][c] = (c < 6) ? qb(fc_w1[c * 48 + k]) : 0.0f;
            }
            if (t < 48) g_qw.bc1[t] = 256.0f * qb(fc_b1[t]);
            for (int i = t; i < 5 * 48; i += 256) {
                int o = i / 48, k = i % 48;
                g_qw.Wc2t[o][k] = qb(fc_w2[k * 5 + o]) * (1.0f / 256.0f);
            }
            if (t < 8) g_qw.bc2[t] = (t < 5) ? qb(fc_b2[t]) : 0.0f;
        }
        return;
    }

    // ---- per-node bn / Ar / As ----
    __shared__ __align__(16) float sW1[32 * 32];
    __shared__ float sb1[32];
    __shared__ float sA[16], sB[16];
    const int b = blk;

    for (int i = t; i < 1024; i += 256) {
        int j = i >> 5, k = i & 31;
        sW1[i] = (k < 30) ? 256.0f * qb(fr_w1[j * 30 + k]) : 0.0f;
    }
    if (t < 32) sb1[t] = (t < 30) ? 256.0f * qb(fr_b1[t]) : 0.0f;
    if (t < 16) {
        float s = gamma[t] / sqrtf(var[t] + 1e-3f);
        sA[t] = s;
        sB[t] = beta[t] - mean[t] * s;
    }
    __syncthreads();

    const int n = t & 127;
    const bool doAr = (t < 128);
    const float* xp = x + (size_t)(b * NN + n) * 16;
    float bn[16];
#pragma unroll
    for (int j = 0; j < 16; j++) bn[j] = xp[j] * sA[j] + sB[j];

    if (doAr) {
        float* bno = &g_bn[(size_t)(b * NN + n) * 16];
#pragma unroll
        for (int j = 0; j < 16; j++) bno[j] = bn[j];
    }

    float acc[32];
#pragma unroll
    for (int k = 0; k < 32; k++) acc[k] = doAr ? sb1[k] : 0.0f;
    const int roff = doAr ? 0 : 16;
#pragma unroll
    for (int j = 0; j < 16; j++) {
        float bj = bn[j];
        const float* wrow = &sW1[(roff + j) * 32];
#pragma unroll
        for (int k = 0; k < 32; k++) acc[k] += bj * wrow[k];
    }
    float* dst = doAr ? &g_Ar[(size_t)(b * NN + n) * 32]
                      : &g_As[(size_t)(b * NN + n) * 32];
#pragma unroll
    for (int k = 0; k < 32; k++) dst[k] = acc[k];
}

// ---------------------------------------------------------------------------
// edge kernel: ONLY the edge MLP + receiver reduction. No node tail — the
// register budget belongs to as[] and the dp4a pipeline alone.
// ---------------------------------------------------------------------------
struct EdgeW { unsigned W2p[15][8]; int b2i[16]; unsigned W3p[6][4]; int b3i[8]; };

__global__ void __launch_bounds__(128) edge_kernel()
{
    __shared__ __align__(16) EdgeW sEw;
    __shared__ __align__(16) float sAr[RT][32];
    __shared__ int sEffI[RT][4];

    const int t = threadIdx.x;
    const int rg = blockIdx.x, b = blockIdx.y;
    const int r0 = rg * RT;

    {
        const uint4* es = reinterpret_cast<const uint4*>(&g_qw);
        uint4* ed = reinterpret_cast<uint4*>(&sEw);
        if (t < 42) ed[t] = es[t];
        const uint4* ars = reinterpret_cast<const uint4*>(&g_Ar[(size_t)(b * NN + r0) * 32]);
        uint4* ard = reinterpret_cast<uint4*>(&sAr[0][0]);
        ard[t] = ars[t];
        if (t < RT * 4) (&sEffI[0][0])[t] = 0;
    }

    // sender activations in registers
    float as[32];
    {
        const float4* p = reinterpret_cast<const float4*>(&g_As[(size_t)(b * NN + t) * 32]);
#pragma unroll
        for (int i = 0; i < 8; i++) {
            float4 v = p[i];
            as[4 * i + 0] = v.x; as[4 * i + 1] = v.y;
            as[4 * i + 2] = v.z; as[4 * i + 3] = v.w;
        }
    }
    __syncthreads();

#pragma unroll 1
    for (int rr = 0; rr < RT; rr++) {
        const float4* a4 = reinterpret_cast<const float4*>(&sAr[rr][0]);

        unsigned h1p[8];
#pragma unroll
        for (int j = 0; j < 8; j++) {
            float4 av = a4[j];     // broadcast LDS
            unsigned u0 = cvt_u8(av.x + as[4 * j + 0]);
            unsigned u1 = cvt_u8(av.y + as[4 * j + 1]);
            unsigned u2 = cvt_u8(av.z + as[4 * j + 2]);
            unsigned u3 = cvt_u8(av.w + as[4 * j + 3]);
            h1p[j] = pk4(u0, u1, u2, u3);
        }

        // layer 2: 15 neurons in groups of 4, packed immediately
        unsigned h2p[4];
#pragma unroll
        for (int g = 0; g < 4; g++) {
            const int nk = (g < 3) ? 4 : 3;
            unsigned qg[4];
#pragma unroll
            for (int u = 0; u < 4; u++) {
                if (u < nk) {
                    int k = g * 4 + u;
                    const uint4* w = reinterpret_cast<const uint4*>(&sEw.W2p[k][0]);
                    uint4 wa = w[0], wb = w[1];
                    int acc = sEw.b2i[k];
                    acc = dp4a_us(h1p[0], wa.x, acc);
                    acc = dp4a_us(h1p[1], wa.y, acc);
                    acc = dp4a_us(h1p[2], wa.z, acc);
                    acc = dp4a_us(h1p[3], wa.w, acc);
                    acc = dp4a_us(h1p[4], wb.x, acc);
                    acc = dp4a_us(h1p[5], wb.y, acc);
                    acc = dp4a_us(h1p[6], wb.z, acc);
                    acc = dp4a_us(h1p[7], wb.w, acc);
                    qg[u] = requant(acc);
                } else {
                    qg[u] = 0u;
                }
            }
            h2p[g] = pk4(qg[0], qg[1], qg[2], qg[3]);
        }

        // layer 3: 6 effect channels
        unsigned e[6];
#pragma unroll
        for (int c = 0; c < 6; c++) {
            uint4 w = *reinterpret_cast<const uint4*>(&sEw.W3p[c][0]);
            int acc = sEw.b3i[c];
            acc = dp4a_us(h2p[0], w.x, acc);
            acc = dp4a_us(h2p[1], w.y, acc);
            acc = dp4a_us(h2p[2], w.z, acc);
            acc = dp4a_us(h2p[3], w.w, acc);
            e[c] = requant(acc);
        }
        const bool diag = (t == r0 + rr);
        int p01 = diag ? 0 : (int)__byte_perm(e[0], e[1], 0x7430);
        int p23 = diag ? 0 : (int)__byte_perm(e[2], e[3], 0x7430);
        int p45 = diag ? 0 : (int)__byte_perm(e[4], e[5], 0x7430);
        p01 = __reduce_add_sync(0xffffffffu, p01);
        p23 = __reduce_add_sync(0xffffffffu, p23);
        p45 = __reduce_add_sync(0xffffffffu, p45);
        if ((t & 31) == 0) {
            atomicAdd(&sEffI[rr][0], p01);
            atomicAdd(&sEffI[rr][1], p23);
            atomicAdd(&sEffI[rr][2], p45);
        }
    }
    __syncthreads();

    // unpack 16-bit halves (each sum <= 127*255 < 2^15) -> g_eff
    if (t < RT * 6) {
        int node = t / 6, c = t % 6;
        int v = sEffI[node][c >> 1];
        float ef = (float)((c & 1) ? ((v >> 16) & 0xFFFF) : (v & 0xFFFF));
        g_eff[(size_t)(b * NN + r0 + node) * 6 + c] = ef;
    }
}

// ---------------------------------------------------------------------------
// node_post kernel: one block per batch row, one thread per node.
// fo MLP in registers, exact-int pooling, head + softmax inline.
// ---------------------------------------------------------------------------
struct FoW {
    float Wo1s[22][48]; float bo1[48];
    float Wo2s[45][24]; float bo2[24];
    float Wo3s[22][8];  float bo3[8];
};

__global__ void __launch_bounds__(128) node_post_kernel(float* __restrict__ out)
{
    __shared__ __align__(16) FoW sFo;
    __shared__ int sPoolI[4];
    __shared__ float sPl[8];
    __shared__ float sc1[48];
    __shared__ float sl[5];

    const int t = threadIdx.x, b = blockIdx.x;

    {
        const uint4* fs = reinterpret_cast<const uint4*>(&g_qw.Wo1s[0][0]);
        uint4* fd = reinterpret_cast<uint4*>(&sFo);
        for (int i = t; i < 598; i += 128) fd[i] = fs[i];
        if (t < 4) sPoolI[t] = 0;
    }
    __syncthreads();

    const int n = t;
    float bn[16];
    {
        const float4* p = reinterpret_cast<const float4*>(&g_bn[(size_t)(b * NN + n) * 16]);
#pragma unroll
        for (int i = 0; i < 4; i++) {
            float4 v = p[i];
            bn[4 * i + 0] = v.x; bn[4 * i + 1] = v.y;
            bn[4 * i + 2] = v.z; bn[4 * i + 3] = v.w;
        }
    }
    float eff[6];
    {
        const float* ep = &g_eff[(size_t)(b * NN + n) * 6];
#pragma unroll
        for (int c = 0; c < 6; c++) eff[c] = ep[c];
    }

    // fo layer 1
    float h1[45];
#pragma unroll
    for (int k = 0; k < 45; k++) {
        float a = sFo.bo1[k];
#pragma unroll
        for (int j = 0; j < 16; j++) a += bn[j] * sFo.Wo1s[j][k];
#pragma unroll
        for (int c = 0; c < 6; c++) a += eff[c] * sFo.Wo1s[16 + c][k];
        h1[k] = qreluF(a);
    }
    // fo layer 2
    float h2[22];
#pragma unroll
    for (int k = 0; k < 22; k++) {
        float a = sFo.bo2[k];
#pragma unroll
        for (int j = 0; j < 45; j++) a += h1[j] * sFo.Wo2s[j][k];
        h2[k] = qreluF(a);
    }
    // fo layer 3 -> integer g values in [0,255]
    int gv[6];
#pragma unroll
    for (int c = 0; c < 6; c++) {
        float a = sFo.bo3[c];
#pragma unroll
        for (int j = 0; j < 22; j++) a += h2[j] * sFo.Wo3s[j][c];
        gv[c] = (int)qreluF(a);
    }

    // exact pooled sum: pack 2x16 (sum over 128 nodes <= 255*128 < 2^15)
    int p01 = gv[0] | (gv[1] << 16);
    int p23 = gv[2] | (gv[3] << 16);
    int p45 = gv[4] | (gv[5] << 16);
    p01 = __reduce_add_sync(0xffffffffu, p01);
    p23 = __reduce_add_sync(0xffffffffu, p23);
    p45 = __reduce_add_sync(0xffffffffu, p45);
    if ((t & 31) == 0) {
        atomicAdd(&sPoolI[0], p01);
        atomicAdd(&sPoolI[1], p23);
        atomicAdd(&sPoolI[2], p45);
    }
    __syncthreads();
    if (t < 6) {
        int v = sPoolI[t >> 1];
        sPl[t] = (float)((t & 1) ? ((v >> 16) & 0xFFFF) : (v & 0xFFFF));
    }
    __syncthreads();

    // head
    if (t < 48) {
        float a = g_qw.bc1[t];
#pragma unroll
        for (int c = 0; c < 6; c++) a += sPl[c] * g_qw.Wc1t[t][c];
        sc1[t] = qreluF(a);
    }
    __syncthreads();
    if (t < 5) {
        float a = g_qw.bc2[t];
#pragma unroll
        for (int k = 0; k < 48; k++) a += sc1[k] * g_qw.Wc2t[t][k];
        sl[t] = a;
    }
    __syncthreads();
    if (t == 0) {
        float m = sl[0];
#pragma unroll
        for (int k = 1; k < 5; k++) m = fmaxf(m, sl[k]);
        float ex[5], sum = 0.0f;
#pragma unroll
        for (int k = 0; k < 5; k++) { ex[k] = expf(sl[k] - m); sum += ex[k]; }
        float inv = 1.0f / sum;
#pragma unroll
        for (int k = 0; k < 5; k++) out[b * 5 + k] = ex[k] * inv;
    }
}

// ---------------------------------------------------------------------------
extern "C" void kernel_launch(void* const* d_in, const int* in_sizes, int n_in,
                              void* d_out, int out_size)
{
    (void)in_sizes; (void)n_in; (void)out_size;

    fused_pre_kernel<<<BB + 4, 256>>>(
        (const float*)d_in[0],
        (const float*)d_in[1],  (const float*)d_in[2],
        (const float*)d_in[3],  (const float*)d_in[4],
        (const float*)d_in[5],  (const float*)d_in[6],
        (const float*)d_in[7],  (const float*)d_in[8],
        (const float*)d_in[9],  (const float*)d_in[10],
        (const float*)d_in[11], (const float*)d_in[12],
        (const float*)d_in[13], (const float*)d_in[14],
        (const float*)d_in[15], (const float*)d_in[16],
        (const float*)d_in[17], (const float*)d_in[18],
        (const float*)d_in[19], (const float*)d_in[20]);

    dim3 grid(NN / RT, BB);
    edge_kernel<<<grid, 128>>>();

    node_post_kernel<<<BB, 128>>>((float*)d_out);
}